// round 1
// baseline (speedup 1.0000x reference)
#include <cuda_runtime.h>
#include <cstdint>
#include <math.h>

// Flash attention, causal, B=2 H=16 S=2048 D=64, fp32 in/out.
// R0 baseline: mma.sync.m16n8k8 tf32 (legacy tensor path), online softmax.
// CTA = 128 threads (4 warps), 64-row Q tile, 64-key KV tiles in smem.

#define SEQ    2048
#define DHEAD  64
#define BQ     64
#define BK     64
#define SKV    68      // smem row stride (words) -> conflict-free fragment reads
#define NBH    32      // B*H

__device__ __forceinline__ uint32_t f2tf32(float f) {
    uint32_t u;
    asm("cvt.rna.tf32.f32 %0, %1;" : "=r"(u) : "f"(f));
    return u;
}

__device__ __forceinline__ void mma_tf32(float c[4], const uint32_t a[4],
                                         uint32_t b0, uint32_t b1) {
    asm volatile(
        "mma.sync.aligned.m16n8k8.row.col.f32.tf32.tf32.f32 "
        "{%0,%1,%2,%3}, {%4,%5,%6,%7}, {%8,%9}, {%0,%1,%2,%3};"
        : "+f"(c[0]), "+f"(c[1]), "+f"(c[2]), "+f"(c[3])
        : "r"(a[0]), "r"(a[1]), "r"(a[2]), "r"(a[3]), "r"(b0), "r"(b1));
}

__global__ __launch_bounds__(128)
void fa_tf32_kernel(const float* __restrict__ Q, const float* __restrict__ K,
                    const float* __restrict__ V, const int* __restrict__ causal_p,
                    const float* __restrict__ scale_p, float* __restrict__ Out) {
    __shared__ float Ks[BK * SKV];   // K tile; reused as P tile after QK^T
    __shared__ float Vs[BK * SKV];

    const int tid  = threadIdx.x;
    const int warp = tid >> 5;
    const int lane = tid & 31;
    const int bh   = blockIdx.y;
    const int n_qtiles = SEQ / BQ;
    const int qtile = n_qtiles - 1 - blockIdx.x;   // heavy tiles first
    const int q0 = qtile * BQ;
    const size_t base = (size_t)bh * SEQ * DHEAD;
    const int causal = *causal_p;
    const float qscale = (*scale_p) * 1.4426950408889634f;  // fold log2(e)

    const int r0 = q0 + warp * 16 + (lane >> 2);   // global q row (c0/c1)
    const int r1 = r0 + 8;                         // global q row (c2/c3)

    // ---- Load Q fragments (pre-scaled, tf32) -------------------------------
    uint32_t qf[8][4];
    {
        const float* qp = Q + base;
        #pragma unroll
        for (int kk = 0; kk < 8; kk++) {
            int c0 = kk * 8 + (lane & 3);
            qf[kk][0] = f2tf32(qp[(size_t)r0 * DHEAD + c0] * qscale);
            qf[kk][1] = f2tf32(qp[(size_t)r1 * DHEAD + c0] * qscale);
            qf[kk][2] = f2tf32(qp[(size_t)r0 * DHEAD + c0 + 4] * qscale);
            qf[kk][3] = f2tf32(qp[(size_t)r1 * DHEAD + c0 + 4] * qscale);
        }
    }

    float o[8][4];
    #pragma unroll
    for (int n = 0; n < 8; n++) { o[n][0]=0.f; o[n][1]=0.f; o[n][2]=0.f; o[n][3]=0.f; }
    float m0 = -INFINITY, m1 = -INFINITY, l0 = 0.f, l1 = 0.f;

    const int ntiles = causal ? (qtile + 1) : n_qtiles;

    for (int t = 0; t < ntiles; t++) {
        const int kbase = t * BK;
        __syncthreads();   // prev iter's P/V reads done before overwrite

        // ---- Load K,V tiles into smem (tf32-rounded) -----------------------
        {
            const float4* Kg = reinterpret_cast<const float4*>(K + base + (size_t)kbase * DHEAD);
            const float4* Vg = reinterpret_cast<const float4*>(V + base + (size_t)kbase * DHEAD);
            #pragma unroll
            for (int i = 0; i < 8; i++) {
                int idx = tid + i * 128;     // 0..1023
                int row = idx >> 4;
                int c4  = idx & 15;
                float4 kv = Kg[row * 16 + c4];
                uint32_t* kd = reinterpret_cast<uint32_t*>(&Ks[row * SKV + c4 * 4]);
                kd[0]=f2tf32(kv.x); kd[1]=f2tf32(kv.y); kd[2]=f2tf32(kv.z); kd[3]=f2tf32(kv.w);
                float4 vv = Vg[row * 16 + c4];
                uint32_t* vd = reinterpret_cast<uint32_t*>(&Vs[row * SKV + c4 * 4]);
                vd[0]=f2tf32(vv.x); vd[1]=f2tf32(vv.y); vd[2]=f2tf32(vv.z); vd[3]=f2tf32(vv.w);
            }
        }
        __syncthreads();

        // ---- S = Q K^T (m16 x n64 x k64 per warp) --------------------------
        float c[8][4];
        const uint32_t* Ksu = reinterpret_cast<const uint32_t*>(Ks);
        #pragma unroll
        for (int n = 0; n < 8; n++) {
            c[n][0]=0.f; c[n][1]=0.f; c[n][2]=0.f; c[n][3]=0.f;
            #pragma unroll
            for (int kk = 0; kk < 8; kk++) {
                // B frag: row(k-dim)=lane%4(+4), col(key)=lane/4
                int key = n * 8 + (lane >> 2);
                int dim = kk * 8 + (lane & 3);
                uint32_t b0 = Ksu[key * SKV + dim];
                uint32_t b1 = Ksu[key * SKV + dim + 4];
                mma_tf32(c[n], qf[kk], b0, b1);
            }
        }

        // ---- Causal mask on diagonal tile ----------------------------------
        if (causal && t == qtile) {
            #pragma unroll
            for (int n = 0; n < 8; n++) {
                int colb = kbase + n * 8 + 2 * (lane & 3);
                if (colb     > r0) c[n][0] = -1e30f;
                if (colb + 1 > r0) c[n][1] = -1e30f;
                if (colb     > r1) c[n][2] = -1e30f;
                if (colb + 1 > r1) c[n][3] = -1e30f;
            }
        }

        // ---- Online softmax (log2 domain) ----------------------------------
        float mr0 = -1e30f, mr1 = -1e30f;
        #pragma unroll
        for (int n = 0; n < 8; n++) {
            mr0 = fmaxf(mr0, fmaxf(c[n][0], c[n][1]));
            mr1 = fmaxf(mr1, fmaxf(c[n][2], c[n][3]));
        }
        mr0 = fmaxf(mr0, __shfl_xor_sync(0xffffffffu, mr0, 1));
        mr0 = fmaxf(mr0, __shfl_xor_sync(0xffffffffu, mr0, 2));
        mr1 = fmaxf(mr1, __shfl_xor_sync(0xffffffffu, mr1, 1));
        mr1 = fmaxf(mr1, __shfl_xor_sync(0xffffffffu, mr1, 2));
        float mn0 = fmaxf(m0, mr0);
        float mn1 = fmaxf(m1, mr1);
        float sf0 = exp2f(m0 - mn0);
        float sf1 = exp2f(m1 - mn1);
        m0 = mn0; m1 = mn1;

        float s0 = 0.f, s1 = 0.f;
        #pragma unroll
        for (int n = 0; n < 8; n++) {
            c[n][0] = exp2f(c[n][0] - mn0);
            c[n][1] = exp2f(c[n][1] - mn0);
            c[n][2] = exp2f(c[n][2] - mn1);
            c[n][3] = exp2f(c[n][3] - mn1);
            s0 += c[n][0] + c[n][1];
            s1 += c[n][2] + c[n][3];
        }
        s0 += __shfl_xor_sync(0xffffffffu, s0, 1);
        s0 += __shfl_xor_sync(0xffffffffu, s0, 2);
        s1 += __shfl_xor_sync(0xffffffffu, s1, 1);
        s1 += __shfl_xor_sync(0xffffffffu, s1, 2);
        l0 = l0 * sf0 + s0;
        l1 = l1 * sf1 + s1;
        #pragma unroll
        for (int n = 0; n < 8; n++) {
            o[n][0] *= sf0; o[n][1] *= sf0; o[n][2] *= sf1; o[n][3] *= sf1;
        }

        // ---- Stage P into (dead) K region, warp-private 16-row slice -------
        __syncthreads();   // everyone done reading K
        uint32_t* Pwu = reinterpret_cast<uint32_t*>(Ks + warp * 16 * SKV);
        {
            int rr = lane >> 2;
            #pragma unroll
            for (int n = 0; n < 8; n++) {
                int col = n * 8 + 2 * (lane & 3);
                Pwu[rr * SKV + col]           = f2tf32(c[n][0]);
                Pwu[rr * SKV + col + 1]       = f2tf32(c[n][1]);
                Pwu[(rr + 8) * SKV + col]     = f2tf32(c[n][2]);
                Pwu[(rr + 8) * SKV + col + 1] = f2tf32(c[n][3]);
            }
        }
        __syncwarp();

        // ---- O += P V (m16 x n64 x k64 per warp) ---------------------------
        const uint32_t* Vsu = reinterpret_cast<const uint32_t*>(Vs);
        #pragma unroll
        for (int kk = 0; kk < 8; kk++) {
            uint32_t a[4];
            int rr = lane >> 2, cc = kk * 8 + (lane & 3);
            a[0] = Pwu[rr * SKV + cc];
            a[1] = Pwu[(rr + 8) * SKV + cc];
            a[2] = Pwu[rr * SKV + cc + 4];
            a[3] = Pwu[(rr + 8) * SKV + cc + 4];
            #pragma unroll
            for (int n = 0; n < 8; n++) {
                int keyr = kk * 8 + (lane & 3);
                int dimc = n * 8 + (lane >> 2);
                uint32_t b0 = Vsu[keyr * SKV + dimc];
                uint32_t b1 = Vsu[(keyr + 4) * SKV + dimc];
                mma_tf32(o[n], a, b0, b1);
            }
        }
    }

    // ---- Epilogue: normalize + store --------------------------------------
    float inv0 = 1.f / l0;
    float inv1 = 1.f / l1;
    float* op = Out + base;
    #pragma unroll
    for (int n = 0; n < 8; n++) {
        int col = n * 8 + 2 * (lane & 3);
        float2 v0 = make_float2(o[n][0] * inv0, o[n][1] * inv0);
        float2 v1 = make_float2(o[n][2] * inv1, o[n][3] * inv1);
        *reinterpret_cast<float2*>(&op[(size_t)r0 * DHEAD + col]) = v0;
        *reinterpret_cast<float2*>(&op[(size_t)r1 * DHEAD + col]) = v1;
    }
}

extern "C" void kernel_launch(void* const* d_in, const int* in_sizes, int n_in,
                              void* d_out, int out_size) {
    const float* Q      = (const float*)d_in[0];
    const float* K      = (const float*)d_in[1];
    const float* V      = (const float*)d_in[2];
    const int*   causal = (const int*)d_in[3];
    const float* scale  = (const float*)d_in[4];
    float* out = (float*)d_out;

    dim3 grid(SEQ / BQ, NBH);   // 32 x 32 CTAs
    fa_tf32_kernel<<<grid, 128>>>(Q, K, V, causal, scale, out);
}

// round 2
// speedup vs baseline: 1.1784x; 1.1784x over previous
#include <cuda_runtime.h>
#include <cstdint>
#include <math.h>

// Flash attention, causal, B=2 H=16 S=2048 D=64, fp32 in/out.
// R2: mma.sync.m16n8k8 tf32, BQ=128 (4 warps x 32 q-rows) -> 2x B-fragment
// reuse; V stride 72 (conflict-free B reads); dedicated P buffer (no mid-loop
// CTA barrier). Dynamic smem = 70656 B.

#define SEQ    2048
#define DHEAD  64
#define BQ     128
#define BK     64
#define SK     68      // K tile stride (words): QK^T B-frag reads conflict-free
#define SV     72      // V tile stride (words): PV  B-frag reads conflict-free
#define SP     68      // P tile stride (words): PV  A-frag reads conflict-free
#define NBH    32      // B*H

#define KS_WORDS (BK * SK)            // 4352
#define VS_WORDS (BK * SV)            // 4608
#define PS_WORDS (BQ * SP)            // 8704
#define SMEM_BYTES ((KS_WORDS + VS_WORDS + PS_WORDS) * 4)   // 70656

__device__ __forceinline__ uint32_t f2tf32(float f) {
    uint32_t u;
    asm("cvt.rna.tf32.f32 %0, %1;" : "=r"(u) : "f"(f));
    return u;
}

__device__ __forceinline__ void mma_tf32(float c[4], const uint32_t a[4],
                                         uint32_t b0, uint32_t b1) {
    asm volatile(
        "mma.sync.aligned.m16n8k8.row.col.f32.tf32.tf32.f32 "
        "{%0,%1,%2,%3}, {%4,%5,%6,%7}, {%8,%9}, {%0,%1,%2,%3};"
        : "+f"(c[0]), "+f"(c[1]), "+f"(c[2]), "+f"(c[3])
        : "r"(a[0]), "r"(a[1]), "r"(a[2]), "r"(a[3]), "r"(b0), "r"(b1));
}

__global__ __launch_bounds__(128, 2)
void fa_tf32_kernel(const float* __restrict__ Q, const float* __restrict__ K,
                    const float* __restrict__ V, const int* __restrict__ causal_p,
                    const float* __restrict__ scale_p, float* __restrict__ Out) {
    extern __shared__ float smem[];
    float* Ks = smem;                       // [BK][SK]
    float* Vs = smem + KS_WORDS;            // [BK][SV]
    float* Ps = smem + KS_WORDS + VS_WORDS; // [BQ][SP]

    const int tid  = threadIdx.x;
    const int warp = tid >> 5;
    const int lane = tid & 31;
    const int bh   = blockIdx.y;
    const int n_qtiles = SEQ / BQ;
    const int qtile = n_qtiles - 1 - blockIdx.x;   // heavy causal tiles first
    const int q0 = qtile * BQ;
    const size_t base = (size_t)bh * SEQ * DHEAD;
    const int causal = *causal_p;
    const float qscale = (*scale_p) * 1.4426950408889634f;  // fold log2(e)

    // q rows per lane: rb in {0,1} row blocks of 16; halves at +0 / +8
    int r[2][2];
    #pragma unroll
    for (int rb = 0; rb < 2; rb++) {
        r[rb][0] = q0 + warp * 32 + rb * 16 + (lane >> 2);
        r[rb][1] = r[rb][0] + 8;
    }

    // ---- Load Q fragments (pre-scaled, tf32) -------------------------------
    uint32_t qf[2][8][4];
    {
        const float* qp = Q + base;
        #pragma unroll
        for (int rb = 0; rb < 2; rb++)
            #pragma unroll
            for (int kk = 0; kk < 8; kk++) {
                int c0 = kk * 8 + (lane & 3);
                qf[rb][kk][0] = f2tf32(qp[(size_t)r[rb][0] * DHEAD + c0] * qscale);
                qf[rb][kk][1] = f2tf32(qp[(size_t)r[rb][1] * DHEAD + c0] * qscale);
                qf[rb][kk][2] = f2tf32(qp[(size_t)r[rb][0] * DHEAD + c0 + 4] * qscale);
                qf[rb][kk][3] = f2tf32(qp[(size_t)r[rb][1] * DHEAD + c0 + 4] * qscale);
            }
    }

    float o[2][8][4];
    #pragma unroll
    for (int rb = 0; rb < 2; rb++)
        #pragma unroll
        for (int n = 0; n < 8; n++) {
            o[rb][n][0] = 0.f; o[rb][n][1] = 0.f; o[rb][n][2] = 0.f; o[rb][n][3] = 0.f;
        }
    float m[2][2] = {{-INFINITY, -INFINITY}, {-INFINITY, -INFINITY}};
    float l[2][2] = {{0.f, 0.f}, {0.f, 0.f}};

    const int ntiles = causal ? (2 * qtile + 2) : (SEQ / BK);

    for (int t = 0; t < ntiles; t++) {
        const int kbase = t * BK;
        __syncthreads();   // protect K/V from overwrite while still in use

        // ---- Fill K,V tiles (tf32-rounded, vectorized stores) --------------
        {
            const float4* Kg = reinterpret_cast<const float4*>(K + base + (size_t)kbase * DHEAD);
            const float4* Vg = reinterpret_cast<const float4*>(V + base + (size_t)kbase * DHEAD);
            #pragma unroll
            for (int i = 0; i < 8; i++) {
                int idx = tid + i * 128;     // 0..1023
                int row = idx >> 4;
                int c4  = idx & 15;
                float4 kv = Kg[row * 16 + c4];
                uint4 kd;
                kd.x = f2tf32(kv.x); kd.y = f2tf32(kv.y); kd.z = f2tf32(kv.z); kd.w = f2tf32(kv.w);
                *reinterpret_cast<uint4*>(&Ks[row * SK + c4 * 4]) = kd;
                float4 vv = Vg[row * 16 + c4];
                uint4 vd;
                vd.x = f2tf32(vv.x); vd.y = f2tf32(vv.y); vd.z = f2tf32(vv.z); vd.w = f2tf32(vv.w);
                *reinterpret_cast<uint4*>(&Vs[row * SV + c4 * 4]) = vd;
            }
        }
        __syncthreads();

        // ---- S = Q K^T  (m32 x n64 x k64 per warp, B frags shared by rb) ---
        float c[2][8][4];
        const uint32_t* Ksu = reinterpret_cast<const uint32_t*>(Ks);
        #pragma unroll
        for (int n = 0; n < 8; n++) {
            #pragma unroll
            for (int rb = 0; rb < 2; rb++) {
                c[rb][n][0]=0.f; c[rb][n][1]=0.f; c[rb][n][2]=0.f; c[rb][n][3]=0.f;
            }
            #pragma unroll
            for (int kk = 0; kk < 8; kk++) {
                int key = n * 8 + (lane >> 2);
                int dim = kk * 8 + (lane & 3);
                uint32_t b0 = Ksu[key * SK + dim];
                uint32_t b1 = Ksu[key * SK + dim + 4];
                mma_tf32(c[0][n], qf[0][kk], b0, b1);
                mma_tf32(c[1][n], qf[1][kk], b0, b1);
            }
        }

        // ---- Causal mask (tiles overlapping the diagonal) ------------------
        if (causal && (kbase + BK - 1 > q0)) {
            #pragma unroll
            for (int rb = 0; rb < 2; rb++)
                #pragma unroll
                for (int n = 0; n < 8; n++) {
                    int colb = kbase + n * 8 + 2 * (lane & 3);
                    if (colb     > r[rb][0]) c[rb][n][0] = -1e30f;
                    if (colb + 1 > r[rb][0]) c[rb][n][1] = -1e30f;
                    if (colb     > r[rb][1]) c[rb][n][2] = -1e30f;
                    if (colb + 1 > r[rb][1]) c[rb][n][3] = -1e30f;
                }
        }

        // ---- Online softmax (log2 domain) ----------------------------------
        #pragma unroll
        for (int rb = 0; rb < 2; rb++) {
            float mr0 = -1e30f, mr1 = -1e30f;
            #pragma unroll
            for (int n = 0; n < 8; n++) {
                mr0 = fmaxf(mr0, fmaxf(c[rb][n][0], c[rb][n][1]));
                mr1 = fmaxf(mr1, fmaxf(c[rb][n][2], c[rb][n][3]));
            }
            mr0 = fmaxf(mr0, __shfl_xor_sync(0xffffffffu, mr0, 1));
            mr0 = fmaxf(mr0, __shfl_xor_sync(0xffffffffu, mr0, 2));
            mr1 = fmaxf(mr1, __shfl_xor_sync(0xffffffffu, mr1, 1));
            mr1 = fmaxf(mr1, __shfl_xor_sync(0xffffffffu, mr1, 2));
            float mn0 = fmaxf(m[rb][0], mr0);
            float mn1 = fmaxf(m[rb][1], mr1);
            float sf0 = exp2f(m[rb][0] - mn0);
            float sf1 = exp2f(m[rb][1] - mn1);
            m[rb][0] = mn0; m[rb][1] = mn1;

            float s0 = 0.f, s1 = 0.f;
            #pragma unroll
            for (int n = 0; n < 8; n++) {
                c[rb][n][0] = exp2f(c[rb][n][0] - mn0);
                c[rb][n][1] = exp2f(c[rb][n][1] - mn0);
                c[rb][n][2] = exp2f(c[rb][n][2] - mn1);
                c[rb][n][3] = exp2f(c[rb][n][3] - mn1);
                s0 += c[rb][n][0] + c[rb][n][1];
                s1 += c[rb][n][2] + c[rb][n][3];
            }
            s0 += __shfl_xor_sync(0xffffffffu, s0, 1);
            s0 += __shfl_xor_sync(0xffffffffu, s0, 2);
            s1 += __shfl_xor_sync(0xffffffffu, s1, 1);
            s1 += __shfl_xor_sync(0xffffffffu, s1, 2);
            l[rb][0] = l[rb][0] * sf0 + s0;
            l[rb][1] = l[rb][1] * sf1 + s1;
            #pragma unroll
            for (int n = 0; n < 8; n++) {
                o[rb][n][0] *= sf0; o[rb][n][1] *= sf0;
                o[rb][n][2] *= sf1; o[rb][n][3] *= sf1;
            }
        }

        // ---- Stage P (warp-private 32-row slice, no CTA barrier) -----------
        uint32_t* Pwu = reinterpret_cast<uint32_t*>(Ps + warp * 32 * SP);
        {
            int rr = lane >> 2;
            #pragma unroll
            for (int rb = 0; rb < 2; rb++)
                #pragma unroll
                for (int n = 0; n < 8; n++) {
                    int col = n * 8 + 2 * (lane & 3);
                    int rB = rb * 16;
                    Pwu[(rB + rr) * SP + col]           = f2tf32(c[rb][n][0]);
                    Pwu[(rB + rr) * SP + col + 1]       = f2tf32(c[rb][n][1]);
                    Pwu[(rB + rr + 8) * SP + col]       = f2tf32(c[rb][n][2]);
                    Pwu[(rB + rr + 8) * SP + col + 1]   = f2tf32(c[rb][n][3]);
                }
        }
        __syncwarp();

        // ---- O += P V  (m32 x n64 x k64 per warp, B frags shared by rb) ----
        const uint32_t* Vsu = reinterpret_cast<const uint32_t*>(Vs);
        #pragma unroll
        for (int kk = 0; kk < 8; kk++) {
            uint32_t a[2][4];
            int rr = lane >> 2, cc = kk * 8 + (lane & 3);
            #pragma unroll
            for (int rb = 0; rb < 2; rb++) {
                int rB = rb * 16;
                a[rb][0] = Pwu[(rB + rr) * SP + cc];
                a[rb][1] = Pwu[(rB + rr + 8) * SP + cc];
                a[rb][2] = Pwu[(rB + rr) * SP + cc + 4];
                a[rb][3] = Pwu[(rB + rr + 8) * SP + cc + 4];
            }
            #pragma unroll
            for (int n = 0; n < 8; n++) {
                int keyr = kk * 8 + (lane & 3);
                int dimc = n * 8 + (lane >> 2);
                uint32_t b0 = Vsu[keyr * SV + dimc];
                uint32_t b1 = Vsu[(keyr + 4) * SV + dimc];
                mma_tf32(o[0][n], a[0], b0, b1);
                mma_tf32(o[1][n], a[1], b0, b1);
            }
        }
    }

    // ---- Epilogue: normalize + store --------------------------------------
    float* op = Out + base;
    #pragma unroll
    for (int rb = 0; rb < 2; rb++) {
        float inv0 = 1.f / l[rb][0];
        float inv1 = 1.f / l[rb][1];
        #pragma unroll
        for (int n = 0; n < 8; n++) {
            int col = n * 8 + 2 * (lane & 3);
            float2 v0 = make_float2(o[rb][n][0] * inv0, o[rb][n][1] * inv0);
            float2 v1 = make_float2(o[rb][n][2] * inv1, o[rb][n][3] * inv1);
            *reinterpret_cast<float2*>(&op[(size_t)r[rb][0] * DHEAD + col]) = v0;
            *reinterpret_cast<float2*>(&op[(size_t)r[rb][1] * DHEAD + col]) = v1;
        }
    }
}

extern "C" void kernel_launch(void* const* d_in, const int* in_sizes, int n_in,
                              void* d_out, int out_size) {
    const float* Q      = (const float*)d_in[0];
    const float* K      = (const float*)d_in[1];
    const float* V      = (const float*)d_in[2];
    const int*   causal = (const int*)d_in[3];
    const float* scale  = (const float*)d_in[4];
    float* out = (float*)d_out;

    cudaFuncSetAttribute(fa_tf32_kernel,
                         cudaFuncAttributeMaxDynamicSharedMemorySize, SMEM_BYTES);

    dim3 grid(SEQ / BQ, NBH);   // 16 x 32 CTAs
    fa_tf32_kernel<<<grid, 128, SMEM_BYTES>>>(Q, K, V, causal, scale, out);
}

// round 3
// speedup vs baseline: 1.4439x; 1.2253x over previous
#include <cuda_runtime.h>
#include <cuda_fp16.h>
#include <cstdint>
#include <math.h>

// Flash attention, causal, B=2 H=16 S=2048 D=64, fp32 in/out.
// R3: mma.sync.m16n8k16 fp16 (fp32 accum). BQ=128 (4 warps x 32 rows).
// K [64x72h], V transposed [64x72h], P fp16 [128x72h]. All mainloop LDS
// conflict-free. Dynamic smem = 36864 B.

#define SEQ    2048
#define DHEAD  64
#define BQ     128
#define BK     64
#define SKH    72     // halves per K row
#define SVH    72     // halves per Vt row (Vt[dim][key])
#define SPH    72     // halves per P row
#define NBH    32

#define KS_HALVES (BK * SKH)     // 4608
#define VS_HALVES (DHEAD * SVH)  // 4608
#define PS_HALVES (BQ * SPH)     // 9216
#define SMEM_BYTES ((KS_HALVES + VS_HALVES + PS_HALVES) * 2)   // 36864

__device__ __forceinline__ void mma_f16(float c[4], const uint32_t a[4],
                                        uint32_t b0, uint32_t b1) {
    asm volatile(
        "mma.sync.aligned.m16n8k16.row.col.f32.f16.f16.f32 "
        "{%0,%1,%2,%3}, {%4,%5,%6,%7}, {%8,%9}, {%0,%1,%2,%3};"
        : "+f"(c[0]), "+f"(c[1]), "+f"(c[2]), "+f"(c[3])
        : "r"(a[0]), "r"(a[1]), "r"(a[2]), "r"(a[3]), "r"(b0), "r"(b1));
}

__device__ __forceinline__ uint32_t pack2(float x, float y) {
    __half2 h = __floats2half2_rn(x, y);
    return *reinterpret_cast<uint32_t*>(&h);
}

__global__ __launch_bounds__(128, 2)
void fa_f16_kernel(const float* __restrict__ Q, const float* __restrict__ K,
                   const float* __restrict__ V, const int* __restrict__ causal_p,
                   const float* __restrict__ scale_p, float* __restrict__ Out) {
    extern __shared__ __half smem[];
    __half* Ks = smem;                          // [BK][SKH]
    __half* Vt = smem + KS_HALVES;              // [DHEAD][SVH] (transposed)
    __half* Ps = smem + KS_HALVES + VS_HALVES;  // [BQ][SPH]

    uint32_t* Ksw = reinterpret_cast<uint32_t*>(Ks);   // half2 granularity
    uint32_t* Vtw = reinterpret_cast<uint32_t*>(Vt);

    const int tid  = threadIdx.x;
    const int warp = tid >> 5;
    const int lane = tid & 31;
    const int bh   = blockIdx.y;
    const int n_qtiles = SEQ / BQ;
    const int qtile = n_qtiles - 1 - blockIdx.x;   // heavy causal tiles first
    const int q0 = qtile * BQ;
    const size_t base = (size_t)bh * SEQ * DHEAD;
    const int causal = *causal_p;
    const float qscale = (*scale_p) * 1.4426950408889634f;  // fold log2(e)

    int r[2][2];
    #pragma unroll
    for (int rb = 0; rb < 2; rb++) {
        r[rb][0] = q0 + warp * 32 + rb * 16 + (lane >> 2);
        r[rb][1] = r[rb][0] + 8;
    }

    // ---- Q fragments (pre-scaled fp16), 4 k16-steps ------------------------
    uint32_t qf[2][4][4];
    {
        const float* qp = Q + base;
        #pragma unroll
        for (int rb = 0; rb < 2; rb++)
            #pragma unroll
            for (int kk = 0; kk < 4; kk++) {
                int d0 = kk * 16 + 2 * (lane & 3);
                const float* p0 = qp + (size_t)r[rb][0] * DHEAD;
                const float* p1 = qp + (size_t)r[rb][1] * DHEAD;
                float2 a0 = *reinterpret_cast<const float2*>(p0 + d0);
                float2 a1 = *reinterpret_cast<const float2*>(p1 + d0);
                float2 a2 = *reinterpret_cast<const float2*>(p0 + d0 + 8);
                float2 a3 = *reinterpret_cast<const float2*>(p1 + d0 + 8);
                qf[rb][kk][0] = pack2(a0.x * qscale, a0.y * qscale);
                qf[rb][kk][1] = pack2(a1.x * qscale, a1.y * qscale);
                qf[rb][kk][2] = pack2(a2.x * qscale, a2.y * qscale);
                qf[rb][kk][3] = pack2(a3.x * qscale, a3.y * qscale);
            }
    }

    float o[2][8][4];
    #pragma unroll
    for (int rb = 0; rb < 2; rb++)
        #pragma unroll
        for (int n = 0; n < 8; n++) {
            o[rb][n][0]=0.f; o[rb][n][1]=0.f; o[rb][n][2]=0.f; o[rb][n][3]=0.f;
        }
    float m[2][2] = {{-INFINITY, -INFINITY}, {-INFINITY, -INFINITY}};
    float l[2][2] = {{0.f, 0.f}, {0.f, 0.f}};

    const int ntiles = causal ? (2 * qtile + 2) : (SEQ / BK);

    for (int t = 0; t < ntiles; t++) {
        const int kbase = t * BK;
        __syncthreads();   // prior tile fully consumed before overwrite

        // ---- Fill K (row-major) ------------------------------------------
        {
            const float4* Kg = reinterpret_cast<const float4*>(K + base + (size_t)kbase * DHEAD);
            #pragma unroll
            for (int i = 0; i < 8; i++) {
                int idx = tid + i * 128;        // 0..1023
                int row = idx >> 4;
                int c4  = idx & 15;
                float4 kv = Kg[row * 16 + c4];
                uint2 hh;
                hh.x = pack2(kv.x, kv.y);
                hh.y = pack2(kv.z, kv.w);
                *reinterpret_cast<uint2*>(&Ks[row * SKH + c4 * 4]) = hh;
            }
        }
        // ---- Fill V transposed: Vt[dim][key], half2 packs key pair --------
        {
            const float4* Vg = reinterpret_cast<const float4*>(V + base + (size_t)kbase * DHEAD);
            int kp = tid & 31;                  // key pair 0..31
            int wg = tid >> 5;                  // dim group of 16
            #pragma unroll
            for (int dd = 0; dd < 4; dd++) {
                int d0 = wg * 16 + dd * 4;
                float4 va = Vg[(2 * kp)     * 16 + (d0 >> 2)];
                float4 vb = Vg[(2 * kp + 1) * 16 + (d0 >> 2)];
                const float* pa = &va.x;
                const float* pb = &vb.x;
                #pragma unroll
                for (int j = 0; j < 4; j++)
                    Vtw[(d0 + j) * (SVH / 2) + kp] = pack2(pa[j], pb[j]);
            }
        }
        __syncthreads();

        // ---- S = Q K^T  (m32 x n64 x k64 per warp) ------------------------
        float c[2][8][4];
        #pragma unroll
        for (int n = 0; n < 8; n++) {
            #pragma unroll
            for (int rb = 0; rb < 2; rb++) {
                c[rb][n][0]=0.f; c[rb][n][1]=0.f; c[rb][n][2]=0.f; c[rb][n][3]=0.f;
            }
            int key = n * 8 + (lane >> 2);
            #pragma unroll
            for (int kk = 0; kk < 4; kk++) {
                int dw = kk * 8 + (lane & 3);     // half2 index in row
                uint32_t b0 = Ksw[key * (SKH / 2) + dw];
                uint32_t b1 = Ksw[key * (SKH / 2) + dw + 4];
                mma_f16(c[0][n], qf[0][kk], b0, b1);
                mma_f16(c[1][n], qf[1][kk], b0, b1);
            }
        }

        // ---- Causal mask ---------------------------------------------------
        if (causal && (kbase + BK - 1 > q0)) {
            #pragma unroll
            for (int rb = 0; rb < 2; rb++)
                #pragma unroll
                for (int n = 0; n < 8; n++) {
                    int colb = kbase + n * 8 + 2 * (lane & 3);
                    if (colb     > r[rb][0]) c[rb][n][0] = -1e30f;
                    if (colb + 1 > r[rb][0]) c[rb][n][1] = -1e30f;
                    if (colb     > r[rb][1]) c[rb][n][2] = -1e30f;
                    if (colb + 1 > r[rb][1]) c[rb][n][3] = -1e30f;
                }
        }

        // ---- Online softmax (log2 domain) ---------------------------------
        #pragma unroll
        for (int rb = 0; rb < 2; rb++) {
            float mr0 = -1e30f, mr1 = -1e30f;
            #pragma unroll
            for (int n = 0; n < 8; n++) {
                mr0 = fmaxf(mr0, fmaxf(c[rb][n][0], c[rb][n][1]));
                mr1 = fmaxf(mr1, fmaxf(c[rb][n][2], c[rb][n][3]));
            }
            mr0 = fmaxf(mr0, __shfl_xor_sync(0xffffffffu, mr0, 1));
            mr0 = fmaxf(mr0, __shfl_xor_sync(0xffffffffu, mr0, 2));
            mr1 = fmaxf(mr1, __shfl_xor_sync(0xffffffffu, mr1, 1));
            mr1 = fmaxf(mr1, __shfl_xor_sync(0xffffffffu, mr1, 2));
            float mn0 = fmaxf(m[rb][0], mr0);
            float mn1 = fmaxf(m[rb][1], mr1);
            float sf0 = exp2f(m[rb][0] - mn0);
            float sf1 = exp2f(m[rb][1] - mn1);
            m[rb][0] = mn0; m[rb][1] = mn1;

            float s0 = 0.f, s1 = 0.f;
            #pragma unroll
            for (int n = 0; n < 8; n++) {
                c[rb][n][0] = exp2f(c[rb][n][0] - mn0);
                c[rb][n][1] = exp2f(c[rb][n][1] - mn0);
                c[rb][n][2] = exp2f(c[rb][n][2] - mn1);
                c[rb][n][3] = exp2f(c[rb][n][3] - mn1);
                s0 += c[rb][n][0] + c[rb][n][1];
                s1 += c[rb][n][2] + c[rb][n][3];
            }
            s0 += __shfl_xor_sync(0xffffffffu, s0, 1);
            s0 += __shfl_xor_sync(0xffffffffu, s0, 2);
            s1 += __shfl_xor_sync(0xffffffffu, s1, 1);
            s1 += __shfl_xor_sync(0xffffffffu, s1, 2);
            l[rb][0] = l[rb][0] * sf0 + s0;
            l[rb][1] = l[rb][1] * sf1 + s1;
            #pragma unroll
            for (int n = 0; n < 8; n++) {
                o[rb][n][0] *= sf0; o[rb][n][1] *= sf0;
                o[rb][n][2] *= sf1; o[rb][n][3] *= sf1;
            }
        }

        // ---- Stage P as fp16 (warp-private rows, no CTA barrier) ----------
        uint32_t* Pw = reinterpret_cast<uint32_t*>(Ps + warp * 32 * SPH);
        {
            int rr = lane >> 2;
            #pragma unroll
            for (int rb = 0; rb < 2; rb++) {
                int rB = rb * 16;
                #pragma unroll
                for (int n = 0; n < 8; n++) {
                    int colw = n * 4 + (lane & 3);   // half2 col index
                    Pw[(rB + rr)     * (SPH / 2) + colw] = pack2(c[rb][n][0], c[rb][n][1]);
                    Pw[(rB + rr + 8) * (SPH / 2) + colw] = pack2(c[rb][n][2], c[rb][n][3]);
                }
            }
        }
        __syncwarp();

        // ---- O += P V  (m32 x n64 x k64 per warp) -------------------------
        #pragma unroll
        for (int kk = 0; kk < 4; kk++) {
            uint32_t a[2][4];
            int rr = lane >> 2;
            int kw = kk * 8 + (lane & 3);       // key half2 index
            #pragma unroll
            for (int rb = 0; rb < 2; rb++) {
                int rB = rb * 16;
                a[rb][0] = Pw[(rB + rr)     * (SPH / 2) + kw];
                a[rb][1] = Pw[(rB + rr + 8) * (SPH / 2) + kw];
                a[rb][2] = Pw[(rB + rr)     * (SPH / 2) + kw + 4];
                a[rb][3] = Pw[(rB + rr + 8) * (SPH / 2) + kw + 4];
            }
            #pragma unroll
            for (int n = 0; n < 8; n++) {
                int dim = n * 8 + (lane >> 2);
                uint32_t b0 = Vtw[dim * (SVH / 2) + kw];
                uint32_t b1 = Vtw[dim * (SVH / 2) + kw + 4];
                mma_f16(o[0][n], a[0], b0, b1);
                mma_f16(o[1][n], a[1], b0, b1);
            }
        }
    }

    // ---- Epilogue ----------------------------------------------------------
    float* op = Out + base;
    #pragma unroll
    for (int rb = 0; rb < 2; rb++) {
        float inv0 = 1.f / l[rb][0];
        float inv1 = 1.f / l[rb][1];
        #pragma unroll
        for (int n = 0; n < 8; n++) {
            int col = n * 8 + 2 * (lane & 3);
            float2 v0 = make_float2(o[rb][n][0] * inv0, o[rb][n][1] * inv0);
            float2 v1 = make_float2(o[rb][n][2] * inv1, o[rb][n][3] * inv1);
            *reinterpret_cast<float2*>(&op[(size_t)r[rb][0] * DHEAD + col]) = v0;
            *reinterpret_cast<float2*>(&op[(size_t)r[rb][1] * DHEAD + col]) = v1;
        }
    }
}

extern "C" void kernel_launch(void* const* d_in, const int* in_sizes, int n_in,
                              void* d_out, int out_size) {
    const float* Q      = (const float*)d_in[0];
    const float* K      = (const float*)d_in[1];
    const float* V      = (const float*)d_in[2];
    const int*   causal = (const int*)d_in[3];
    const float* scale  = (const float*)d_in[4];
    float* out = (float*)d_out;

    cudaFuncSetAttribute(fa_f16_kernel,
                         cudaFuncAttributeMaxDynamicSharedMemorySize, SMEM_BYTES);

    dim3 grid(SEQ / BQ, NBH);   // 16 x 32 CTAs
    fa_f16_kernel<<<grid, 128, SMEM_BYTES>>>(Q, K, V, causal, scale, out);
}

// round 6
// speedup vs baseline: 1.4460x; 1.0015x over previous
#include <cuda_runtime.h>
#include <cuda_fp16.h>
#include <cstdint>
#include <math.h>

// Flash attention, causal, B=2 H=16 S=2048 D=64, fp32 in/out.
// R5: R3 fp16 mma.sync kernel + cp.async double-buffered raw K/V staging.
// Raw fp32 tiles prefetched 1 tile ahead (LDGSTS); converted smem->smem to
// fp16 K [64x72h] and transposed Vt [64x72h]; P fp16 [128x72h].
// Mainloop LDS layouts identical to R3 (verified conflict-free).

#define SEQ 2048
#define DH  64
#define BQ  128
#define BK  64
#define NBH 32

// byte offsets in dynamic smem
#define OFF_K0 0                    // raw K fp32, 64 rows x 64 floats (16384 B)
#define OFF_K1 16384
#define OFF_V0 32768                // raw V fp32, 64 rows x 68-word stride (17408 B)
#define OFF_V1 50176
#define OFF_KS 67584                // K fp16 [64][72h]  (9216 B)
#define OFF_VT 76800                // Vt fp16 [64][72h] (9216 B)
#define OFF_P  86016                // P fp16 [128][72h] (18432 B)
#define SMEM_TOTAL 104448

#define VRAW_STRIDE_B 272           // 68 words per raw V row

__device__ __forceinline__ uint32_t s2u(const void* p) {
    uint32_t a;
    asm("{ .reg .u64 t; cvta.to.shared.u64 t, %1; cvt.u32.u64 %0, t; }" : "=r"(a) : "l"(p));
    return a;
}
__device__ __forceinline__ uint32_t pack2(float x, float y) {
    __half2 h = __floats2half2_rn(x, y);
    return *reinterpret_cast<uint32_t*>(&h);
}
__device__ __forceinline__ void cpa16(uint32_t dst, const void* src) {
    asm volatile("cp.async.cg.shared.global [%0], [%1], 16;" :: "r"(dst), "l"(src));
}
__device__ __forceinline__ void mma_f16(float c[4], const uint32_t a[4],
                                        uint32_t b0, uint32_t b1) {
    asm volatile(
        "mma.sync.aligned.m16n8k16.row.col.f32.f16.f16.f32 "
        "{%0,%1,%2,%3}, {%4,%5,%6,%7}, {%8,%9}, {%0,%1,%2,%3};"
        : "+f"(c[0]), "+f"(c[1]), "+f"(c[2]), "+f"(c[3])
        : "r"(a[0]), "r"(a[1]), "r"(a[2]), "r"(a[3]), "r"(b0), "r"(b1));
}

// Stage one K,V tile (fp32) into raw buffers via cp.async (per-thread chunks).
__device__ __forceinline__ void stage_kv(uint32_t sb, int buf,
                                         const float* __restrict__ Kg,
                                         const float* __restrict__ Vg,
                                         int tid, int wid, int lane) {
    uint32_t kdst = sb + (buf ? OFF_K1 : OFF_K0);
    #pragma unroll
    for (int i = 0; i < 8; i++) {
        int idx = tid + i * 128;                   // 16B chunk id, 0..1023
        cpa16(kdst + idx * 16, Kg + idx * 4);
    }
    uint32_t vdst = sb + (buf ? OFF_V1 : OFF_V0);
    #pragma unroll
    for (int a = 0; a < 2; a++) {
        int row = 2 * lane + a;                    // key row 0..63
        #pragma unroll
        for (int dd = 0; dd < 4; dd++) {
            int colf = wid * 16 + dd * 4;          // float col
            cpa16(vdst + row * VRAW_STRIDE_B + colf * 4,
                  Vg + row * DH + colf);
        }
    }
}

__global__ __launch_bounds__(128, 2)
void fa_f16_kernel(const float* __restrict__ Q, const float* __restrict__ K,
                   const float* __restrict__ V, const int* __restrict__ causal_p,
                   const float* __restrict__ scale_p, float* __restrict__ Out) {
    extern __shared__ char smem[];
    const uint32_t sb = s2u(smem);

    uint32_t*       Ksw = reinterpret_cast<uint32_t*>(smem + OFF_KS);  // half2 words, stride 36
    uint32_t*       Vtw = reinterpret_cast<uint32_t*>(smem + OFF_VT);  // half2 words, stride 36

    const int tid  = threadIdx.x;
    const int wid  = tid >> 5;
    const int lane = tid & 31;
    const int bh   = blockIdx.y;
    const int n_qtiles = SEQ / BQ;
    const int qtile = n_qtiles - 1 - blockIdx.x;   // heavy causal tiles first
    const int q0 = qtile * BQ;
    const size_t base = (size_t)bh * SEQ * DH;
    const int causal = *causal_p;
    const float qscale = (*scale_p) * 1.4426950408889634f;

    int r[2][2];
    #pragma unroll
    for (int rb = 0; rb < 2; rb++) {
        r[rb][0] = q0 + wid * 32 + rb * 16 + (lane >> 2);
        r[rb][1] = r[rb][0] + 8;
    }

    // ---- Prefetch tile 0 ---------------------------------------------------
    stage_kv(sb, 0, K + base, V + base, tid, wid, lane);
    asm volatile("cp.async.commit_group;" ::: "memory");

    // ---- Q fragments (pre-scaled fp16), 4 k16-steps ------------------------
    uint32_t qf[2][4][4];
    {
        const float* qp = Q + base;
        #pragma unroll
        for (int rb = 0; rb < 2; rb++)
            #pragma unroll
            for (int kk = 0; kk < 4; kk++) {
                int d0 = kk * 16 + 2 * (lane & 3);
                const float* p0 = qp + (size_t)r[rb][0] * DH;
                const float* p1 = qp + (size_t)r[rb][1] * DH;
                float2 a0 = *reinterpret_cast<const float2*>(p0 + d0);
                float2 a1 = *reinterpret_cast<const float2*>(p1 + d0);
                float2 a2 = *reinterpret_cast<const float2*>(p0 + d0 + 8);
                float2 a3 = *reinterpret_cast<const float2*>(p1 + d0 + 8);
                qf[rb][kk][0] = pack2(a0.x * qscale, a0.y * qscale);
                qf[rb][kk][1] = pack2(a1.x * qscale, a1.y * qscale);
                qf[rb][kk][2] = pack2(a2.x * qscale, a2.y * qscale);
                qf[rb][kk][3] = pack2(a3.x * qscale, a3.y * qscale);
            }
    }

    float o[2][8][4];
    #pragma unroll
    for (int rb = 0; rb < 2; rb++)
        #pragma unroll
        for (int n = 0; n < 8; n++) {
            o[rb][n][0]=0.f; o[rb][n][1]=0.f; o[rb][n][2]=0.f; o[rb][n][3]=0.f;
        }
    float m[2][2] = {{-INFINITY, -INFINITY}, {-INFINITY, -INFINITY}};
    float l[2][2] = {{0.f, 0.f}, {0.f, 0.f}};

    const int ntiles = causal ? (2 * qtile + 2) : (SEQ / BK);

    for (int t = 0; t < ntiles; t++) {
        const int kb = t * BK;
        const int buf = t & 1;

        // ---- Prefetch t+1, then wait for t's raw data ----------------------
        if (t + 1 < ntiles) {
            stage_kv(sb, buf ^ 1,
                     K + base + (size_t)(kb + BK) * DH,
                     V + base + (size_t)(kb + BK) * DH, tid, wid, lane);
            asm volatile("cp.async.commit_group;" ::: "memory");
            asm volatile("cp.async.wait_group 1;" ::: "memory");
        } else {
            asm volatile("cp.async.wait_group 0;" ::: "memory");
        }

        // ---- Convert own K chunks: raw fp32 -> Ks fp16 [64][72h] -----------
        {
            const char* kraw = smem + (buf ? OFF_K1 : OFF_K0);
            #pragma unroll
            for (int i = 0; i < 8; i++) {
                int idx = tid + i * 128;
                int row = idx >> 4, c4 = idx & 15;
                float4 v = *reinterpret_cast<const float4*>(kraw + idx * 16);
                uint2 h;
                h.x = pack2(v.x, v.y);
                h.y = pack2(v.z, v.w);
                *reinterpret_cast<uint2*>(smem + OFF_KS + row * 144 + c4 * 8) = h;
            }
        }
        // ---- Transpose own V chunks: raw fp32 -> Vt fp16 [dim][keypair] ----
        {
            const char* vraw = smem + (buf ? OFF_V1 : OFF_V0);
            float4 va[4], vb[4];
            #pragma unroll
            for (int dd = 0; dd < 4; dd++) {
                int colb = (wid * 16 + dd * 4) * 4;
                va[dd] = *reinterpret_cast<const float4*>(vraw + (2 * lane)     * VRAW_STRIDE_B + colb);
                vb[dd] = *reinterpret_cast<const float4*>(vraw + (2 * lane + 1) * VRAW_STRIDE_B + colb);
            }
            #pragma unroll
            for (int dd = 0; dd < 4; dd++) {
                int d0 = wid * 16 + dd * 4;
                const float* pa = &va[dd].x;
                const float* pb = &vb[dd].x;
                #pragma unroll
                for (int j = 0; j < 4; j++)
                    Vtw[(d0 + j) * 36 + lane] = pack2(pa[j], pb[j]);
            }
        }
        __syncthreads();

        // ---- S = Q K^T  (m32 x n64 x k64 per warp) ------------------------
        float c[2][8][4];
        #pragma unroll
        for (int n = 0; n < 8; n++) {
            #pragma unroll
            for (int rb = 0; rb < 2; rb++) {
                c[rb][n][0]=0.f; c[rb][n][1]=0.f; c[rb][n][2]=0.f; c[rb][n][3]=0.f;
            }
            int key = n * 8 + (lane >> 2);
            #pragma unroll
            for (int kk = 0; kk < 4; kk++) {
                int dw = kk * 8 + (lane & 3);
                uint32_t b0 = Ksw[key * 36 + dw];
                uint32_t b1 = Ksw[key * 36 + dw + 4];
                mma_f16(c[0][n], qf[0][kk], b0, b1);
                mma_f16(c[1][n], qf[1][kk], b0, b1);
            }
        }

        // ---- Causal mask ---------------------------------------------------
        if (causal && (kb + BK - 1 > q0)) {
            #pragma unroll
            for (int rb = 0; rb < 2; rb++)
                #pragma unroll
                for (int n = 0; n < 8; n++) {
                    int colb = kb + n * 8 + 2 * (lane & 3);
                    if (colb     > r[rb][0]) c[rb][n][0] = -1e30f;
                    if (colb + 1 > r[rb][0]) c[rb][n][1] = -1e30f;
                    if (colb     > r[rb][1]) c[rb][n][2] = -1e30f;
                    if (colb + 1 > r[rb][1]) c[rb][n][3] = -1e30f;
                }
        }

        // ---- Online softmax (log2 domain) ---------------------------------
        #pragma unroll
        for (int rb = 0; rb < 2; rb++) {
            float mr0 = -1e30f, mr1 = -1e30f;
            #pragma unroll
            for (int n = 0; n < 8; n++) {
                mr0 = fmaxf(mr0, fmaxf(c[rb][n][0], c[rb][n][1]));
                mr1 = fmaxf(mr1, fmaxf(c[rb][n][2], c[rb][n][3]));
            }
            mr0 = fmaxf(mr0, __shfl_xor_sync(0xffffffffu, mr0, 1));
            mr0 = fmaxf(mr0, __shfl_xor_sync(0xffffffffu, mr0, 2));
            mr1 = fmaxf(mr1, __shfl_xor_sync(0xffffffffu, mr1, 1));
            mr1 = fmaxf(mr1, __shfl_xor_sync(0xffffffffu, mr1, 2));
            float mn0 = fmaxf(m[rb][0], mr0);
            float mn1 = fmaxf(m[rb][1], mr1);
            float sf0 = exp2f(m[rb][0] - mn0);
            float sf1 = exp2f(m[rb][1] - mn1);
            m[rb][0] = mn0; m[rb][1] = mn1;

            float s0 = 0.f, s1 = 0.f;
            #pragma unroll
            for (int n = 0; n < 8; n++) {
                c[rb][n][0] = exp2f(c[rb][n][0] - mn0);
                c[rb][n][1] = exp2f(c[rb][n][1] - mn0);
                c[rb][n][2] = exp2f(c[rb][n][2] - mn1);
                c[rb][n][3] = exp2f(c[rb][n][3] - mn1);
                s0 += c[rb][n][0] + c[rb][n][1];
                s1 += c[rb][n][2] + c[rb][n][3];
            }
            s0 += __shfl_xor_sync(0xffffffffu, s0, 1);
            s0 += __shfl_xor_sync(0xffffffffu, s0, 2);
            s1 += __shfl_xor_sync(0xffffffffu, s1, 1);
            s1 += __shfl_xor_sync(0xffffffffu, s1, 2);
            l[rb][0] = l[rb][0] * sf0 + s0;
            l[rb][1] = l[rb][1] * sf1 + s1;
            #pragma unroll
            for (int n = 0; n < 8; n++) {
                o[rb][n][0] *= sf0; o[rb][n][1] *= sf0;
                o[rb][n][2] *= sf1; o[rb][n][3] *= sf1;
            }
        }

        // ---- Stage P fp16 (warp-private rows) ------------------------------
        uint32_t* Pw = reinterpret_cast<uint32_t*>(smem + OFF_P + wid * 32 * 144);
        {
            int rr = lane >> 2;
            #pragma unroll
            for (int rb = 0; rb < 2; rb++) {
                int rB = rb * 16;
                #pragma unroll
                for (int n = 0; n < 8; n++) {
                    int colw = n * 4 + (lane & 3);
                    Pw[(rB + rr)     * 36 + colw] = pack2(c[rb][n][0], c[rb][n][1]);
                    Pw[(rB + rr + 8) * 36 + colw] = pack2(c[rb][n][2], c[rb][n][3]);
                }
            }
        }
        __syncwarp();

        // ---- O += P V  (m32 x n64 x k64 per warp) -------------------------
        #pragma unroll
        for (int kk = 0; kk < 4; kk++) {
            uint32_t a[2][4];
            int rr = lane >> 2;
            int kw = kk * 8 + (lane & 3);
            #pragma unroll
            for (int rb = 0; rb < 2; rb++) {
                int rB = rb * 16;
                a[rb][0] = Pw[(rB + rr)     * 36 + kw];
                a[rb][1] = Pw[(rB + rr + 8) * 36 + kw];
                a[rb][2] = Pw[(rB + rr)     * 36 + kw + 4];
                a[rb][3] = Pw[(rB + rr + 8) * 36 + kw + 4];
            }
            #pragma unroll
            for (int n = 0; n < 8; n++) {
                int dim = n * 8 + (lane >> 2);
                uint32_t b0 = Vtw[dim * 36 + kw];
                uint32_t b1 = Vtw[dim * 36 + kw + 4];
                mma_f16(o[0][n], a[0], b0, b1);
                mma_f16(o[1][n], a[1], b0, b1);
            }
        }
        __syncthreads();   // protect Ks/Vt from next tile's convert
    }

    // ---- Epilogue ----------------------------------------------------------
    float* op = Out + base;
    #pragma unroll
    for (int rb = 0; rb < 2; rb++) {
        float inv0 = 1.f / l[rb][0];
        float inv1 = 1.f / l[rb][1];
        #pragma unroll
        for (int n = 0; n < 8; n++) {
            int col = n * 8 + 2 * (lane & 3);
            float2 v0 = make_float2(o[rb][n][0] * inv0, o[rb][n][1] * inv0);
            float2 v1 = make_float2(o[rb][n][2] * inv1, o[rb][n][3] * inv1);
            *reinterpret_cast<float2*>(&op[(size_t)r[rb][0] * DH + col]) = v0;
            *reinterpret_cast<float2*>(&op[(size_t)r[rb][1] * DH + col]) = v1;
        }
    }
}

extern "C" void kernel_launch(void* const* d_in, const int* in_sizes, int n_in,
                              void* d_out, int out_size) {
    const float* Q      = (const float*)d_in[0];
    const float* K      = (const float*)d_in[1];
    const float* V      = (const float*)d_in[2];
    const int*   causal = (const int*)d_in[3];
    const float* scale  = (const float*)d_in[4];
    float* out = (float*)d_out;

    cudaFuncSetAttribute(fa_f16_kernel,
                         cudaFuncAttributeMaxDynamicSharedMemorySize, SMEM_TOTAL);

    dim3 grid(SEQ / BQ, NBH);   // 16 x 32 CTAs
    fa_f16_kernel<<<grid, 128, SMEM_TOTAL>>>(Q, K, V, causal, scale, out);
}